// round 14
// baseline (speedup 1.0000x reference)
#include <cuda_runtime.h>
#include <cstdint>

#define FULLMASK 0xFFFFFFFFu

#define DIMN   5
#define NSAVE  64
#define BATCH  4096
#define EPSV   1e-6f
#define DT0V   0.1f
#define NELEM  3     // elements per warp
#define WPB    3     // warps per CTA: 456 CTAs = exactly 3 per SM (152 SMs)
#define NTHR   (WPB * 32)

#define A21f 0.161f
#define A31f -0.008480655492356989f
#define A32f 0.335480655492357f
#define A41f 2.8971530571054935f
#define A42f -6.359448489975075f
#define A43f 4.3622954328695815f
#define A51f 5.325864828439257f
#define A52f -11.748883564062828f
#define A53f 7.4955393428898365f
#define A54f -0.09249506636175525f
#define A61f 5.86145544294642f
#define A62f -12.92096931784711f
#define A63f 8.159367898576159f
#define A64f -0.071584973281401f
#define A65f -0.028269050394068383f
#define B1f 0.09646076681806523f
#define B2f 0.01f
#define B3f 0.4798896504144996f
#define B4f 1.379008574103742f
#define B5f -3.290069515436081f
#define B6f 2.324710524099774f
#define E1f -0.00178001105222577714f
#define E2f -0.0008164344596567469f
#define E3f 0.007880878010261995f
#define E4f -0.1447110071732629f
#define E5f 0.5823571654525552f
#define E6f -0.45808210592918697f
#define E7f 0.015151515151515152f

// fast softplus (MUFU.EX2/LG2), abs err ~1e-7 — far inside the 1e-3 gate
static __device__ __forceinline__ float spf(float x) {
    return fmaxf(x, 0.0f) + __logf(1.0f + __expf(-fabsf(x)));
}

static __device__ __forceinline__ void fma2(unsigned long long &d,
                                            unsigned long long a,
                                            unsigned long long b) {
    asm("fma.rn.f32x2 %0, %1, %2, %0;" : "+l"(d) : "l"(a), "l"(b));
}
static __device__ __forceinline__ float2 asf2(unsigned long long u) {
    float2 f;
    asm("mov.b64 {%0, %1}, %2;" : "=f"(f.x), "=f"(f.y) : "l"(u));
    return f;
}

// 64->64 layer for THREE elements sharing one warp's weight loads.
// Lane j -> output neurons j, j+32. Wrow stride 68 floats (conflict-free LDS.128).
// Reduction loop is unroll-4 ON PURPOSE: the surviving back-edge bounds ptxas
// load batching, keeping transient register demand small (R11: full unroll ->
// 255 regs; unroll-4 -> ~150 regs, no spills).
static __device__ __forceinline__ void layer64x3(const float* __restrict__ Wrow,
                                                 const float* __restrict__ bsm,
                                                 const float* __restrict__ hbuf, // [3][64]
                                                 int j, float2 out[NELEM]) {
    const ulonglong2* w0 = reinterpret_cast<const ulonglong2*>(Wrow + j * 68);
    const ulonglong2* w1 = reinterpret_cast<const ulonglong2*>(Wrow + (j + 32) * 68);
    const ulonglong2* h0p = reinterpret_cast<const ulonglong2*>(hbuf);
    const ulonglong2* h1p = reinterpret_cast<const ulonglong2*>(hbuf + 64);
    const ulonglong2* h2p = reinterpret_cast<const ulonglong2*>(hbuf + 128);
    unsigned long long A0 = 0ull, A1 = 0ull, A2 = 0ull, A3 = 0ull;
    unsigned long long B0 = 0ull, B1 = 0ull, B2 = 0ull, B3 = 0ull;
    unsigned long long C0 = 0ull, C1 = 0ull, C2 = 0ull, C3 = 0ull;
#pragma unroll 4
    for (int c = 0; c < 16; ++c) {
        const ulonglong2 wa = w0[c];
        const ulonglong2 wb = w1[c];
        const ulonglong2 xa = h0p[c];
        const ulonglong2 xb = h1p[c];
        const ulonglong2 xc = h2p[c];
        fma2(A0, wa.x, xa.x); fma2(A1, wa.y, xa.y);
        fma2(A2, wb.x, xa.x); fma2(A3, wb.y, xa.y);
        fma2(B0, wa.x, xb.x); fma2(B1, wa.y, xb.y);
        fma2(B2, wb.x, xb.x); fma2(B3, wb.y, xb.y);
        fma2(C0, wa.x, xc.x); fma2(C1, wa.y, xc.y);
        fma2(C2, wb.x, xc.x); fma2(C3, wb.y, xc.y);
    }
    const float bj = bsm[j], bj2 = bsm[j + 32];
    {
        const float2 f0 = asf2(A0), f1 = asf2(A1), f2 = asf2(A2), f3 = asf2(A3);
        out[0].x = bj  + ((f0.x + f0.y) + (f1.x + f1.y));
        out[0].y = bj2 + ((f2.x + f2.y) + (f3.x + f3.y));
    }
    {
        const float2 f0 = asf2(B0), f1 = asf2(B1), f2 = asf2(B2), f3 = asf2(B3);
        out[1].x = bj  + ((f0.x + f0.y) + (f1.x + f1.y));
        out[1].y = bj2 + ((f2.x + f2.y) + (f3.x + f3.y));
    }
    {
        const float2 f0 = asf2(C0), f1 = asf2(C1), f2 = asf2(C2), f3 = asf2(C3);
        out[2].x = bj  + ((f0.x + f0.y) + (f1.x + f1.y));
        out[2].y = bj2 + ((f2.x + f2.y) + (f3.x + f3.y));
    }
}

// MLP for 3 elements. Stage inputs read from per-warp smem yax[e*8+d] (broadcast);
// result kk[e] lane-sliced: lane j<5 ends holding dim j.
static __device__ __forceinline__ void feval3(const float* __restrict__ yax,
                                              float kk[NELEM],
                                              const float* __restrict__ sW1,
                                              const float* __restrict__ sb1,
                                              const float* __restrict__ sW2,
                                              const float* __restrict__ sb2,
                                              const float* __restrict__ sW3,
                                              const float* __restrict__ sb3,
                                              const float2* __restrict__ sW4,
                                              const float* __restrict__ sb4,
                                              float* __restrict__ buf0,
                                              float* __restrict__ buf1, int j) {
    __syncwarp();   // make lanes 0..4's yax stores visible
    // layer 1: 5 -> 64
    {
        const float b0 = sb1[j], b1 = sb1[j + 32];
        float w0r[DIMN], w1r[DIMN];
#pragma unroll
        for (int i = 0; i < DIMN; ++i) {
            w0r[i] = sW1[j * DIMN + i];
            w1r[i] = sW1[(j + 32) * DIMN + i];
        }
#pragma unroll
        for (int e = 0; e < NELEM; ++e) {
            const float4 x4 = *reinterpret_cast<const float4*>(yax + e * 8);
            const float x5 = yax[e * 8 + 4];
            float a0 = b0, a1 = b1;
            a0 = fmaf(w0r[0], x4.x, a0); a1 = fmaf(w1r[0], x4.x, a1);
            a0 = fmaf(w0r[1], x4.y, a0); a1 = fmaf(w1r[1], x4.y, a1);
            a0 = fmaf(w0r[2], x4.z, a0); a1 = fmaf(w1r[2], x4.z, a1);
            a0 = fmaf(w0r[3], x4.w, a0); a1 = fmaf(w1r[3], x4.w, a1);
            a0 = fmaf(w0r[4], x5, a0);   a1 = fmaf(w1r[4], x5, a1);
            buf0[e * 64 + j] = spf(a0);
            buf0[e * 64 + 32 + j] = spf(a1);
        }
    }
    __syncwarp();
    float2 r[NELEM];
    layer64x3(sW2, sb2, buf0, j, r);
#pragma unroll
    for (int e = 0; e < NELEM; ++e) {
        buf1[e * 64 + j] = spf(r[e].x);
        buf1[e * 64 + 32 + j] = spf(r[e].y);
    }
    __syncwarp();
    layer64x3(sW3, sb3, buf1, j, r);
    float h0[NELEM], h1[NELEM];
#pragma unroll
    for (int e = 0; e < NELEM; ++e) { h0[e] = spf(r[e].x); h1[e] = spf(r[e].y); }
    // layer 4: 64 -> 5, butterfly; lane o keeps output o
#pragma unroll
    for (int o = 0; o < DIMN; ++o) {
        const float2 w = sW4[o * 32 + j];
        float p[NELEM];
#pragma unroll
        for (int e = 0; e < NELEM; ++e) p[e] = fmaf(w.x, h0[e], w.y * h1[e]);
#pragma unroll
        for (int s = 16; s > 0; s >>= 1)
#pragma unroll
            for (int e = 0; e < NELEM; ++e)
                p[e] += __shfl_xor_sync(FULLMASK, p[e], s);
        if (j == o) {
#pragma unroll
            for (int e = 0; e < NELEM; ++e) kk[e] = p[e] + sb4[o];
        }
    }
}

__global__ void __launch_bounds__(NTHR)
node_tsit5_kernel(const float* __restrict__ y0g, const float* __restrict__ teg,
                  const float* __restrict__ W1g, const float* __restrict__ b1g,
                  const float* __restrict__ W2g, const float* __restrict__ b2g,
                  const float* __restrict__ W3g, const float* __restrict__ b3g,
                  const float* __restrict__ W4g, const float* __restrict__ b4g,
                  float* __restrict__ outg) {
    __shared__ __align__(16) float sW2[64 * 68];
    __shared__ __align__(16) float sW3[64 * 68];
    __shared__ __align__(16) float sW1[64 * DIMN];
    __shared__ float sb1[64], sb2[64], sb3[64];
    __shared__ __align__(8) float2 sW4[DIMN * 32];
    __shared__ float sb4[8];
    __shared__ __align__(16) float ssh[WPB][2 * NELEM][64];  // per-warp h buffers
    __shared__ __align__(16) float syax[WPB][NELEM][8];      // per-warp stage inputs
    __shared__ __align__(16) float ssc[WPB][NELEM][32];      // per-warp interp scratch

    const int tid = threadIdx.x;
    for (int e = tid; e < 64 * 16; e += NTHR) {
        const int r = e >> 4, c = e & 15;
        reinterpret_cast<float4*>(sW2 + r * 68)[c] = reinterpret_cast<const float4*>(W2g)[e];
        reinterpret_cast<float4*>(sW3 + r * 68)[c] = reinterpret_cast<const float4*>(W3g)[e];
    }
    for (int e = tid; e < 64 * DIMN; e += NTHR) sW1[e] = W1g[e];
    if (tid < 64) { sb1[tid] = b1g[tid]; sb2[tid] = b2g[tid]; sb3[tid] = b3g[tid]; }
    if (tid < 8) sb4[tid] = (tid < DIMN) ? b4g[tid] : 0.0f;
    for (int e = tid; e < DIMN * 32; e += NTHR) {
        const int o = e >> 5, jj = e & 31;
        sW4[e] = make_float2(W4g[o * 64 + jj], W4g[o * 64 + jj + 32]);
    }
    __syncthreads();

    const int warp = tid >> 5;
    const int j = tid & 31;
    const int bA = (blockIdx.x * WPB + warp) * NELEM;
    float* buf0 = &ssh[warp][0][0];
    float* buf1 = &ssh[warp][NELEM][0];
    float* yax  = &syax[warp][0][0];
    float* scc  = &ssc[warp][0][0];

    bool valid[NELEM];
#pragma unroll
    for (int e = 0; e < NELEM; ++e) valid[e] = (bA + e) < BATCH;

    const float te0 = teg[j];
    const float te1 = teg[j + 32];
    const float t0 = __shfl_sync(FULLMASK, te0, 0);
    const float t1 = __shfl_sync(FULLMASK, te1, 31);

    // lane-sliced y: lane j<5 holds dim j (0 elsewhere / invalid, never escapes)
    float y[NELEM];
#pragma unroll
    for (int e = 0; e < NELEM; ++e)
        y[e] = (valid[e] && j < DIMN) ? y0g[(bA + e) * DIMN + j] : 0.0f;

    // initial save fill (matches reference init)
#pragma unroll
    for (int e = 0; e < NELEM; ++e) {
        if (!valid[e]) continue;
        const float* y0e = y0g + (bA + e) * DIMN;
        float* outb = outg + (size_t)(bA + e) * NSAVE * DIMN;
        const bool m0 = (te0 <= t0 + EPSV);
        const bool m1 = (te1 <= t0 + EPSV);
#pragma unroll
        for (int d = 0; d < DIMN; ++d) {
            const float v = y0e[d];
            outb[j * DIMN + d] = m0 ? v : 0.0f;
            outb[(j + 32) * DIMN + d] = m1 ? v : 0.0f;
        }
    }

    float t[NELEM], hs[NELEM];
    float k1[NELEM], k2[NELEM], k3[NELEM], k4[NELEM], k5[NELEM], k6[NELEM], k7[NELEM];
#pragma unroll
    for (int e = 0; e < NELEM; ++e) {
        t[e] = valid[e] ? t0 : t1;   // invalid elements are born done
        hs[e] = DT0V;
        k1[e] = k2[e] = k3[e] = k4[e] = k5[e] = k6[e] = k7[e] = 0.0f;
    }

    float yn[NELEM], hc[NELEM];
    bool dn[NELEM];

    // FSAL seed
    if (j < DIMN) {
#pragma unroll
        for (int e = 0; e < NELEM; ++e) yax[e * 8 + j] = y[e];
    }
    feval3(yax, k1, sW1, sb1, sW2, sb2, sW3, sb3, sW4, sb4, buf0, buf1, j);

    for (int it = 0; it < 64; ++it) {
        bool alldone = true;
#pragma unroll
        for (int e = 0; e < NELEM; ++e) {
            dn[e] = (t[e] >= t1 - EPSV);
            alldone = alldone && dn[e];
        }
        if (alldone) break;
#pragma unroll
        for (int e = 0; e < NELEM; ++e)
            hc[e] = dn[e] ? 0.0f : fminf(hs[e], t1 - t[e]);

#pragma unroll
        for (int e = 0; e < NELEM; ++e) {
            const float v = y[e] + hc[e] * (A21f * k1[e]);
            if (j < DIMN) yax[e * 8 + j] = v;
        }
        feval3(yax, k2, sW1, sb1, sW2, sb2, sW3, sb3, sW4, sb4, buf0, buf1, j);
#pragma unroll
        for (int e = 0; e < NELEM; ++e) {
            const float v = y[e] + hc[e] * (A31f * k1[e] + A32f * k2[e]);
            if (j < DIMN) yax[e * 8 + j] = v;
        }
        feval3(yax, k3, sW1, sb1, sW2, sb2, sW3, sb3, sW4, sb4, buf0, buf1, j);
#pragma unroll
        for (int e = 0; e < NELEM; ++e) {
            const float v = y[e] + hc[e] * (A41f * k1[e] + A42f * k2[e] + A43f * k3[e]);
            if (j < DIMN) yax[e * 8 + j] = v;
        }
        feval3(yax, k4, sW1, sb1, sW2, sb2, sW3, sb3, sW4, sb4, buf0, buf1, j);
#pragma unroll
        for (int e = 0; e < NELEM; ++e) {
            const float v = y[e] + hc[e] * (A51f * k1[e] + A52f * k2[e] +
                                            A53f * k3[e] + A54f * k4[e]);
            if (j < DIMN) yax[e * 8 + j] = v;
        }
        feval3(yax, k5, sW1, sb1, sW2, sb2, sW3, sb3, sW4, sb4, buf0, buf1, j);
#pragma unroll
        for (int e = 0; e < NELEM; ++e) {
            const float v = y[e] + hc[e] * (A61f * k1[e] + A62f * k2[e] + A63f * k3[e] +
                                            A64f * k4[e] + A65f * k5[e]);
            if (j < DIMN) yax[e * 8 + j] = v;
        }
        feval3(yax, k6, sW1, sb1, sW2, sb2, sW3, sb3, sW4, sb4, buf0, buf1, j);
#pragma unroll
        for (int e = 0; e < NELEM; ++e) {
            yn[e] = y[e] + hc[e] * (B1f * k1[e] + B2f * k2[e] + B3f * k3[e] +
                                    B4f * k4[e] + B5f * k5[e] + B6f * k6[e]);
            if (j < DIMN) yax[e * 8 + j] = yn[e];
        }
        feval3(yax, k7, sW1, sb1, sW2, sb2, sW3, sb3, sW4, sb4, buf0, buf1, j);

#pragma unroll
        for (int e = 0; e < NELEM; ++e) {
            const float err = hc[e] * (E1f * k1[e] + E2f * k2[e] + E3f * k3[e] +
                                       E4f * k4[e] + E5f * k5[e] + E6f * k6[e] +
                                       E7f * k7[e]);
            const float sc = 1e-6f + 1e-3f * fmaxf(fabsf(y[e]), fabsf(yn[e]));
            const float q = err / sc;
            const float q2 = q * q;
            float ss = __shfl_sync(FULLMASK, q2, 0);
            ss += __shfl_sync(FULLMASK, q2, 1);
            ss += __shfl_sync(FULLMASK, q2, 2);
            ss += __shfl_sync(FULLMASK, q2, 3);
            ss += __shfl_sync(FULLMASK, q2, 4);
            const float enorm = sqrtf(ss * 0.2f);
            const bool accept = (enorm <= 1.0f);
            const float ec = fmaxf(enorm, 1e-10f);
            const float factor = fminf(fmaxf(0.9f * powf(ec, -0.2f), 0.2f), 10.0f);

            if (!dn[e] && accept) {   // warp-uniform
                const float tn = t[e] + hc[e];
                float* s = scc + e * 32;  // [0:8)=y [8:16)=yn [16:24)=hc*k1 [24:32)=hc*k7
                if (j < DIMN) {
                    s[j] = y[e];
                    s[8 + j] = yn[e];
                    s[16 + j] = hc[e] * k1[e];
                    s[24 + j] = hc[e] * k7[e];
                }
                __syncwarp();
                const float inv = 1.0f / fmaxf(hc[e], 1e-12f);
                float* outb = outg + (size_t)(bA + e) * NSAVE * DIMN;
                if (te0 > t[e] && te0 <= tn + EPSV) {
                    const float sv = (te0 - t[e]) * inv, s2 = sv * sv, s3 = s2 * sv;
                    const float h00 = 2.f * s3 - 3.f * s2 + 1.f;
                    const float h10 = s3 - 2.f * s2 + sv;
                    const float h01 = -2.f * s3 + 3.f * s2;
                    const float h11 = s3 - s2;
#pragma unroll
                    for (int d = 0; d < DIMN; ++d)
                        outb[j * DIMN + d] = h00 * s[d] + h10 * s[16 + d] +
                                             h01 * s[8 + d] + h11 * s[24 + d];
                }
                if (te1 > t[e] && te1 <= tn + EPSV) {
                    const float sv = (te1 - t[e]) * inv, s2 = sv * sv, s3 = s2 * sv;
                    const float h00 = 2.f * s3 - 3.f * s2 + 1.f;
                    const float h10 = s3 - 2.f * s2 + sv;
                    const float h01 = -2.f * s3 + 3.f * s2;
                    const float h11 = s3 - s2;
#pragma unroll
                    for (int d = 0; d < DIMN; ++d)
                        outb[(j + 32) * DIMN + d] = h00 * s[d] + h10 * s[16 + d] +
                                                    h01 * s[8 + d] + h11 * s[24 + d];
                }
                y[e] = yn[e];
                k1[e] = k7[e];   // FSAL
                t[e] = tn;
            }
            if (!dn[e]) hs[e] = hc[e] * factor;
        }
    }
}

extern "C" void kernel_launch(void* const* d_in, const int* in_sizes, int n_in,
                              void* d_out, int out_size) {
    const float* y0 = (const float*)d_in[0];
    const float* te = (const float*)d_in[1];
    const float* W1 = (const float*)d_in[2];
    const float* b1 = (const float*)d_in[3];
    const float* W2 = (const float*)d_in[4];
    const float* b2 = (const float*)d_in[5];
    const float* W3 = (const float*)d_in[6];
    const float* b3 = (const float*)d_in[7];
    const float* W4 = (const float*)d_in[8];
    const float* b4 = (const float*)d_in[9];
    float* out = (float*)d_out;
    // 3 elements/warp, 3 warps/CTA -> 9 elements/CTA; grid 456 = exactly 3 CTAs/SM
    const int grid = (BATCH + WPB * NELEM - 1) / (WPB * NELEM);
    node_tsit5_kernel<<<grid, NTHR>>>(y0, te, W1, b1, W2, b2, W3, b3, W4, b4, out);
}

// round 15
// speedup vs baseline: 1.1289x; 1.1289x over previous
#include <cuda_runtime.h>
#include <cstdint>

#define FULLMASK 0xFFFFFFFFu

#define DIMN   5
#define NSAVE  64
#define BATCH  4096
#define EPSV   1e-6f
#define DT0V   0.1f
#define NELEM  4     // elements per warp; 2 warps/CTA -> 8/CTA, grid 512, no tail

#define A21f 0.161f
#define A31f -0.008480655492356989f
#define A32f 0.335480655492357f
#define A41f 2.8971530571054935f
#define A42f -6.359448489975075f
#define A43f 4.3622954328695815f
#define A51f 5.325864828439257f
#define A52f -11.748883564062828f
#define A53f 7.4955393428898365f
#define A54f -0.09249506636175525f
#define A61f 5.86145544294642f
#define A62f -12.92096931784711f
#define A63f 8.159367898576159f
#define A64f -0.071584973281401f
#define A65f -0.028269050394068383f
#define B1f 0.09646076681806523f
#define B2f 0.01f
#define B3f 0.4798896504144996f
#define B4f 1.379008574103742f
#define B5f -3.290069515436081f
#define B6f 2.324710524099774f
#define E1f -0.00178001105222577714f
#define E2f -0.0008164344596567469f
#define E3f 0.007880878010261995f
#define E4f -0.1447110071732629f
#define E5f 0.5823571654525552f
#define E6f -0.45808210592918697f
#define E7f 0.015151515151515152f

// fast softplus (MUFU.EX2/LG2), abs err ~1e-7 — far inside the 1e-3 gate
static __device__ __forceinline__ float spf(float x) {
    return fmaxf(x, 0.0f) + __logf(1.0f + __expf(-fabsf(x)));
}

static __device__ __forceinline__ void fma2(unsigned long long &d,
                                            unsigned long long a,
                                            unsigned long long b) {
    asm("fma.rn.f32x2 %0, %1, %2, %0;" : "+l"(d) : "l"(a), "l"(b));
}
static __device__ __forceinline__ float2 asf2(unsigned long long u) {
    float2 f;
    asm("mov.b64 {%0, %1}, %2;" : "=f"(f.x), "=f"(f.y) : "l"(u));
    return f;
}

// 64->64 layer for FOUR elements sharing one warp's weight loads.
// Lane j -> output neurons j, j+32. Wrow stride 68 floats (conflict-free LDS.128).
// Reduction loop is unroll-4 ON PURPOSE: the surviving back-edge bounds ptxas
// load batching, keeping transient register demand small (R11: full unroll ->
// 255 regs; unroll-4 -> ~130-160 regs, no spills).
static __device__ __forceinline__ void layer64x4(const float* __restrict__ Wrow,
                                                 const float* __restrict__ bsm,
                                                 const float* __restrict__ hbuf, // [4][64]
                                                 int j, float2 out[NELEM]) {
    const ulonglong2* w0 = reinterpret_cast<const ulonglong2*>(Wrow + j * 68);
    const ulonglong2* w1 = reinterpret_cast<const ulonglong2*>(Wrow + (j + 32) * 68);
    const ulonglong2* h0p = reinterpret_cast<const ulonglong2*>(hbuf);
    const ulonglong2* h1p = reinterpret_cast<const ulonglong2*>(hbuf + 64);
    const ulonglong2* h2p = reinterpret_cast<const ulonglong2*>(hbuf + 128);
    const ulonglong2* h3p = reinterpret_cast<const ulonglong2*>(hbuf + 192);
    unsigned long long A0 = 0ull, A1 = 0ull, A2 = 0ull, A3 = 0ull;
    unsigned long long B0 = 0ull, B1 = 0ull, B2 = 0ull, B3 = 0ull;
    unsigned long long C0 = 0ull, C1 = 0ull, C2 = 0ull, C3 = 0ull;
    unsigned long long D0 = 0ull, D1 = 0ull, D2 = 0ull, D3 = 0ull;
#pragma unroll 4
    for (int c = 0; c < 16; ++c) {
        const ulonglong2 wa = w0[c];
        const ulonglong2 wb = w1[c];
        const ulonglong2 xa = h0p[c];
        const ulonglong2 xb = h1p[c];
        const ulonglong2 xc = h2p[c];
        const ulonglong2 xd = h3p[c];
        fma2(A0, wa.x, xa.x); fma2(A1, wa.y, xa.y);
        fma2(A2, wb.x, xa.x); fma2(A3, wb.y, xa.y);
        fma2(B0, wa.x, xb.x); fma2(B1, wa.y, xb.y);
        fma2(B2, wb.x, xb.x); fma2(B3, wb.y, xb.y);
        fma2(C0, wa.x, xc.x); fma2(C1, wa.y, xc.y);
        fma2(C2, wb.x, xc.x); fma2(C3, wb.y, xc.y);
        fma2(D0, wa.x, xd.x); fma2(D1, wa.y, xd.y);
        fma2(D2, wb.x, xd.x); fma2(D3, wb.y, xd.y);
    }
    const float bj = bsm[j], bj2 = bsm[j + 32];
    {
        const float2 f0 = asf2(A0), f1 = asf2(A1), f2 = asf2(A2), f3 = asf2(A3);
        out[0].x = bj  + ((f0.x + f0.y) + (f1.x + f1.y));
        out[0].y = bj2 + ((f2.x + f2.y) + (f3.x + f3.y));
    }
    {
        const float2 f0 = asf2(B0), f1 = asf2(B1), f2 = asf2(B2), f3 = asf2(B3);
        out[1].x = bj  + ((f0.x + f0.y) + (f1.x + f1.y));
        out[1].y = bj2 + ((f2.x + f2.y) + (f3.x + f3.y));
    }
    {
        const float2 f0 = asf2(C0), f1 = asf2(C1), f2 = asf2(C2), f3 = asf2(C3);
        out[2].x = bj  + ((f0.x + f0.y) + (f1.x + f1.y));
        out[2].y = bj2 + ((f2.x + f2.y) + (f3.x + f3.y));
    }
    {
        const float2 f0 = asf2(D0), f1 = asf2(D1), f2 = asf2(D2), f3 = asf2(D3);
        out[3].x = bj  + ((f0.x + f0.y) + (f1.x + f1.y));
        out[3].y = bj2 + ((f2.x + f2.y) + (f3.x + f3.y));
    }
}

// MLP for 4 elements. Stage inputs read from per-warp smem yax[e*8+d] (broadcast);
// result kk[e] lane-sliced: lane j<5 ends holding dim j.
static __device__ __forceinline__ void feval4(const float* __restrict__ yax,
                                              float kk[NELEM],
                                              const float* __restrict__ sW1,
                                              const float* __restrict__ sb1,
                                              const float* __restrict__ sW2,
                                              const float* __restrict__ sb2,
                                              const float* __restrict__ sW3,
                                              const float* __restrict__ sb3,
                                              const float2* __restrict__ sW4,
                                              const float* __restrict__ sb4,
                                              float* __restrict__ buf0,
                                              float* __restrict__ buf1, int j) {
    __syncwarp();   // make lanes 0..4's yax stores visible
    // layer 1: 5 -> 64
    {
        const float b0 = sb1[j], b1 = sb1[j + 32];
        float w0r[DIMN], w1r[DIMN];
#pragma unroll
        for (int i = 0; i < DIMN; ++i) {
            w0r[i] = sW1[j * DIMN + i];
            w1r[i] = sW1[(j + 32) * DIMN + i];
        }
#pragma unroll
        for (int e = 0; e < NELEM; ++e) {
            const float4 x4 = *reinterpret_cast<const float4*>(yax + e * 8);
            const float x5 = yax[e * 8 + 4];
            float a0 = b0, a1 = b1;
            a0 = fmaf(w0r[0], x4.x, a0); a1 = fmaf(w1r[0], x4.x, a1);
            a0 = fmaf(w0r[1], x4.y, a0); a1 = fmaf(w1r[1], x4.y, a1);
            a0 = fmaf(w0r[2], x4.z, a0); a1 = fmaf(w1r[2], x4.z, a1);
            a0 = fmaf(w0r[3], x4.w, a0); a1 = fmaf(w1r[3], x4.w, a1);
            a0 = fmaf(w0r[4], x5, a0);   a1 = fmaf(w1r[4], x5, a1);
            buf0[e * 64 + j] = spf(a0);
            buf0[e * 64 + 32 + j] = spf(a1);
        }
    }
    __syncwarp();
    float2 r[NELEM];
    layer64x4(sW2, sb2, buf0, j, r);
#pragma unroll
    for (int e = 0; e < NELEM; ++e) {
        buf1[e * 64 + j] = spf(r[e].x);
        buf1[e * 64 + 32 + j] = spf(r[e].y);
    }
    __syncwarp();
    layer64x4(sW3, sb3, buf1, j, r);
    float h0[NELEM], h1[NELEM];
#pragma unroll
    for (int e = 0; e < NELEM; ++e) { h0[e] = spf(r[e].x); h1[e] = spf(r[e].y); }
    // layer 4: 64 -> 5, butterfly; lane o keeps output o
#pragma unroll
    for (int o = 0; o < DIMN; ++o) {
        const float2 w = sW4[o * 32 + j];
        float p[NELEM];
#pragma unroll
        for (int e = 0; e < NELEM; ++e) p[e] = fmaf(w.x, h0[e], w.y * h1[e]);
#pragma unroll
        for (int s = 16; s > 0; s >>= 1)
#pragma unroll
            for (int e = 0; e < NELEM; ++e)
                p[e] += __shfl_xor_sync(FULLMASK, p[e], s);
        if (j == o) {
#pragma unroll
            for (int e = 0; e < NELEM; ++e) kk[e] = p[e] + sb4[o];
        }
    }
}

__global__ void __launch_bounds__(64)
node_tsit5_kernel(const float* __restrict__ y0g, const float* __restrict__ teg,
                  const float* __restrict__ W1g, const float* __restrict__ b1g,
                  const float* __restrict__ W2g, const float* __restrict__ b2g,
                  const float* __restrict__ W3g, const float* __restrict__ b3g,
                  const float* __restrict__ W4g, const float* __restrict__ b4g,
                  float* __restrict__ outg) {
    __shared__ __align__(16) float sW2[64 * 68];
    __shared__ __align__(16) float sW3[64 * 68];
    __shared__ __align__(16) float sW1[64 * DIMN];
    __shared__ float sb1[64], sb2[64], sb3[64];
    __shared__ __align__(8) float2 sW4[DIMN * 32];
    __shared__ float sb4[8];
    __shared__ __align__(16) float ssh[2][2 * NELEM][64];  // per-warp h buffers
    __shared__ __align__(16) float syax[2][NELEM][8];      // per-warp stage inputs
    __shared__ __align__(16) float ssc[2][NELEM][32];      // per-warp interp scratch

    const int tid = threadIdx.x;
    for (int e = tid; e < 64 * 16; e += 64) {
        const int r = e >> 4, c = e & 15;
        reinterpret_cast<float4*>(sW2 + r * 68)[c] = reinterpret_cast<const float4*>(W2g)[e];
        reinterpret_cast<float4*>(sW3 + r * 68)[c] = reinterpret_cast<const float4*>(W3g)[e];
    }
    for (int e = tid; e < 64 * DIMN; e += 64) sW1[e] = W1g[e];
    sb1[tid] = b1g[tid]; sb2[tid] = b2g[tid]; sb3[tid] = b3g[tid];
    if (tid < 8) sb4[tid] = (tid < DIMN) ? b4g[tid] : 0.0f;
    for (int e = tid; e < DIMN * 32; e += 64) {
        const int o = e >> 5, jj = e & 31;
        sW4[e] = make_float2(W4g[o * 64 + jj], W4g[o * 64 + jj + 32]);
    }
    __syncthreads();

    const int warp = tid >> 5;
    const int j = tid & 31;
    const int bA = (blockIdx.x * 2 + warp) * NELEM;   // 4096 = 512*8, no tail
    float* buf0 = &ssh[warp][0][0];
    float* buf1 = &ssh[warp][NELEM][0];
    float* yax  = &syax[warp][0][0];
    float* scc  = &ssc[warp][0][0];

    const float te0 = teg[j];
    const float te1 = teg[j + 32];
    const float t0 = __shfl_sync(FULLMASK, te0, 0);
    const float t1 = __shfl_sync(FULLMASK, te1, 31);

    // lane-sliced y: lane j<5 holds dim j (0 elsewhere, never escapes)
    float y[NELEM];
#pragma unroll
    for (int e = 0; e < NELEM; ++e)
        y[e] = (j < DIMN) ? y0g[(bA + e) * DIMN + j] : 0.0f;

    // initial save fill (matches reference init)
#pragma unroll
    for (int e = 0; e < NELEM; ++e) {
        const float* y0e = y0g + (bA + e) * DIMN;
        float* outb = outg + (size_t)(bA + e) * NSAVE * DIMN;
        const bool m0 = (te0 <= t0 + EPSV);
        const bool m1 = (te1 <= t0 + EPSV);
#pragma unroll
        for (int d = 0; d < DIMN; ++d) {
            const float v = y0e[d];
            outb[j * DIMN + d] = m0 ? v : 0.0f;
            outb[(j + 32) * DIMN + d] = m1 ? v : 0.0f;
        }
    }

    float t[NELEM], hs[NELEM];
    float k1[NELEM], k2[NELEM], k3[NELEM], k4[NELEM], k5[NELEM], k6[NELEM], k7[NELEM];
#pragma unroll
    for (int e = 0; e < NELEM; ++e) {
        t[e] = t0; hs[e] = DT0V;
        k1[e] = k2[e] = k3[e] = k4[e] = k5[e] = k6[e] = k7[e] = 0.0f;
    }

    float yn[NELEM], hc[NELEM];
    bool dn[NELEM];

    // FSAL seed
    if (j < DIMN) {
#pragma unroll
        for (int e = 0; e < NELEM; ++e) yax[e * 8 + j] = y[e];
    }
    feval4(yax, k1, sW1, sb1, sW2, sb2, sW3, sb3, sW4, sb4, buf0, buf1, j);

    for (int it = 0; it < 64; ++it) {
        bool alldone = true;
#pragma unroll
        for (int e = 0; e < NELEM; ++e) {
            dn[e] = (t[e] >= t1 - EPSV);
            alldone = alldone && dn[e];
        }
        if (alldone) break;
#pragma unroll
        for (int e = 0; e < NELEM; ++e)
            hc[e] = dn[e] ? 0.0f : fminf(hs[e], t1 - t[e]);

#pragma unroll
        for (int e = 0; e < NELEM; ++e) {
            const float v = y[e] + hc[e] * (A21f * k1[e]);
            if (j < DIMN) yax[e * 8 + j] = v;
        }
        feval4(yax, k2, sW1, sb1, sW2, sb2, sW3, sb3, sW4, sb4, buf0, buf1, j);
#pragma unroll
        for (int e = 0; e < NELEM; ++e) {
            const float v = y[e] + hc[e] * (A31f * k1[e] + A32f * k2[e]);
            if (j < DIMN) yax[e * 8 + j] = v;
        }
        feval4(yax, k3, sW1, sb1, sW2, sb2, sW3, sb3, sW4, sb4, buf0, buf1, j);
#pragma unroll
        for (int e = 0; e < NELEM; ++e) {
            const float v = y[e] + hc[e] * (A41f * k1[e] + A42f * k2[e] + A43f * k3[e]);
            if (j < DIMN) yax[e * 8 + j] = v;
        }
        feval4(yax, k4, sW1, sb1, sW2, sb2, sW3, sb3, sW4, sb4, buf0, buf1, j);
#pragma unroll
        for (int e = 0; e < NELEM; ++e) {
            const float v = y[e] + hc[e] * (A51f * k1[e] + A52f * k2[e] +
                                            A53f * k3[e] + A54f * k4[e]);
            if (j < DIMN) yax[e * 8 + j] = v;
        }
        feval4(yax, k5, sW1, sb1, sW2, sb2, sW3, sb3, sW4, sb4, buf0, buf1, j);
#pragma unroll
        for (int e = 0; e < NELEM; ++e) {
            const float v = y[e] + hc[e] * (A61f * k1[e] + A62f * k2[e] + A63f * k3[e] +
                                            A64f * k4[e] + A65f * k5[e]);
            if (j < DIMN) yax[e * 8 + j] = v;
        }
        feval4(yax, k6, sW1, sb1, sW2, sb2, sW3, sb3, sW4, sb4, buf0, buf1, j);
#pragma unroll
        for (int e = 0; e < NELEM; ++e) {
            yn[e] = y[e] + hc[e] * (B1f * k1[e] + B2f * k2[e] + B3f * k3[e] +
                                    B4f * k4[e] + B5f * k5[e] + B6f * k6[e]);
            if (j < DIMN) yax[e * 8 + j] = yn[e];
        }
        feval4(yax, k7, sW1, sb1, sW2, sb2, sW3, sb3, sW4, sb4, buf0, buf1, j);

#pragma unroll
        for (int e = 0; e < NELEM; ++e) {
            const float err = hc[e] * (E1f * k1[e] + E2f * k2[e] + E3f * k3[e] +
                                       E4f * k4[e] + E5f * k5[e] + E6f * k6[e] +
                                       E7f * k7[e]);
            const float sc = 1e-6f + 1e-3f * fmaxf(fabsf(y[e]), fabsf(yn[e]));
            const float q = err / sc;
            const float q2 = q * q;
            float ss = __shfl_sync(FULLMASK, q2, 0);
            ss += __shfl_sync(FULLMASK, q2, 1);
            ss += __shfl_sync(FULLMASK, q2, 2);
            ss += __shfl_sync(FULLMASK, q2, 3);
            ss += __shfl_sync(FULLMASK, q2, 4);
            const float enorm = sqrtf(ss * 0.2f);
            const bool accept = (enorm <= 1.0f);
            const float ec = fmaxf(enorm, 1e-10f);
            // fast pow: exp(-0.2*log(ec)) via MUFU; factor perturbation ~1e-6,
            // only scales the next trial step -> far inside the 1e-3 gate
            const float factor = fminf(fmaxf(0.9f * __expf(-0.2f * __logf(ec)), 0.2f), 10.0f);

            if (!dn[e] && accept) {   // warp-uniform
                const float tn = t[e] + hc[e];
                float* s = scc + e * 32;  // [0:8)=y [8:16)=yn [16:24)=hc*k1 [24:32)=hc*k7
                if (j < DIMN) {
                    s[j] = y[e];
                    s[8 + j] = yn[e];
                    s[16 + j] = hc[e] * k1[e];
                    s[24 + j] = hc[e] * k7[e];
                }
                __syncwarp();
                const float inv = 1.0f / fmaxf(hc[e], 1e-12f);
                float* outb = outg + (size_t)(bA + e) * NSAVE * DIMN;
                if (te0 > t[e] && te0 <= tn + EPSV) {
                    const float sv = (te0 - t[e]) * inv, s2 = sv * sv, s3 = s2 * sv;
                    const float h00 = 2.f * s3 - 3.f * s2 + 1.f;
                    const float h10 = s3 - 2.f * s2 + sv;
                    const float h01 = -2.f * s3 + 3.f * s2;
                    const float h11 = s3 - s2;
#pragma unroll
                    for (int d = 0; d < DIMN; ++d)
                        outb[j * DIMN + d] = h00 * s[d] + h10 * s[16 + d] +
                                             h01 * s[8 + d] + h11 * s[24 + d];
                }
                if (te1 > t[e] && te1 <= tn + EPSV) {
                    const float sv = (te1 - t[e]) * inv, s2 = sv * sv, s3 = s2 * sv;
                    const float h00 = 2.f * s3 - 3.f * s2 + 1.f;
                    const float h10 = s3 - 2.f * s2 + sv;
                    const float h01 = -2.f * s3 + 3.f * s2;
                    const float h11 = s3 - s2;
#pragma unroll
                    for (int d = 0; d < DIMN; ++d)
                        outb[(j + 32) * DIMN + d] = h00 * s[d] + h10 * s[16 + d] +
                                                    h01 * s[8 + d] + h11 * s[24 + d];
                }
                y[e] = yn[e];
                k1[e] = k7[e];   // FSAL
                t[e] = tn;
            }
            if (!dn[e]) hs[e] = hc[e] * factor;
        }
    }
}

extern "C" void kernel_launch(void* const* d_in, const int* in_sizes, int n_in,
                              void* d_out, int out_size) {
    const float* y0 = (const float*)d_in[0];
    const float* te = (const float*)d_in[1];
    const float* W1 = (const float*)d_in[2];
    const float* b1 = (const float*)d_in[3];
    const float* W2 = (const float*)d_in[4];
    const float* b2 = (const float*)d_in[5];
    const float* W3 = (const float*)d_in[6];
    const float* b3 = (const float*)d_in[7];
    const float* W4 = (const float*)d_in[8];
    const float* b4 = (const float*)d_in[9];
    float* out = (float*)d_out;
    // 4 elements/warp, 2 warps/CTA -> 8 elements/CTA; grid 512 exact (4096 = 512*8)
    node_tsit5_kernel<<<BATCH / (2 * NELEM), 64>>>(y0, te, W1, b1, W2, b2, W3, b3, W4, b4, out);
}